// round 2
// baseline (speedup 1.0000x reference)
#include <cuda_runtime.h>
#include <cuda_bf16.h>
#include <cstdint>

#define Bb   16
#define LAT  8
#define NPTS 500000
#define XS   256
#define HALF 128
#define IMG_ELEMS (Bb * XS * XS)   // 1,048,576

// ---------------- device scratch (static, no runtime allocation) ------------
__device__ float  g_img[IMG_ELEMS];     // 4 MB
__device__ float  g_tmp[IMG_ELEMS];     // 4 MB
__device__ float2 g_F[IMG_ELEMS];       // 8 MB
__device__ float  g_R[Bb * 6];          // rows 0,1 of each rotation matrix
__device__ float  g_sh[Bb * 2];
__device__ float  g_h[Bb * LAT];
__device__ float2 g_tw[128];            // exp(-2*pi*i*k/256), k=0..127

// ---------------- prep: rotations, shifts, MLP h, twiddles ------------------
// R entries computed with explicit non-contracted fp32 ops to match XLA's
// elementwise fusion (separate mul/sub roundings, no FMA contraction).
__global__ void prep_kernel(const float* __restrict__ rows,
                            const float* __restrict__ shifts,
                            const float* __restrict__ latent,
                            const float* __restrict__ W0, const float* __restrict__ b0,
                            const float* __restrict__ W1, const float* __restrict__ b1,
                            const float* __restrict__ W2, const float* __restrict__ b2,
                            const float* __restrict__ W3, const float* __restrict__ b3)
{
    int t = threadIdx.x;
    if (t < 128) {
        float ang = -6.283185307179586f * (float)t / 256.0f;
        float s, c;
        sincosf(ang, &s, &c);
        g_tw[t] = make_float2(c, s);
    }
    if (t < Bb) {
        int b = t;
        float rot = rows[b*3+0], tilt = rows[b*3+1], psi = rows[b*3+2];
        float ca = cosf(rot),  sa = sinf(rot);
        float cb = cosf(tilt), sb = sinf(tilt);
        float cg = cosf(psi),  sg = sinf(psi);
        // Row 0: [cg*cb*ca - sg*sa,  cg*cb*sa + sg*ca,  -cg*sb]
        float cgcb = __fmul_rn(cg, cb);
        g_R[b*6+0] = __fsub_rn(__fmul_rn(cgcb, ca), __fmul_rn(sg, sa));
        g_R[b*6+1] = __fadd_rn(__fmul_rn(cgcb, sa), __fmul_rn(sg, ca));
        g_R[b*6+2] = __fmul_rn(-cg, sb);
        // Row 1: [-sg*cb*ca - cg*sa,  -sg*cb*sa + cg*ca,  sg*sb]
        float msgcb = __fmul_rn(-sg, cb);
        g_R[b*6+3] = __fsub_rn(__fmul_rn(msgcb, ca), __fmul_rn(cg, sa));
        g_R[b*6+4] = __fadd_rn(__fmul_rn(msgcb, sa), __fmul_rn(cg, ca));
        g_R[b*6+5] = __fmul_rn(sg, sb);
        g_sh[b*2+0] = shifts[b*2+0];
        g_sh[b*2+1] = shifts[b*2+1];

        float h[LAT], l[LAT], tv[LAT];
        for (int i = 0; i < LAT; i++) l[i] = latent[b*LAT+i];
        for (int j = 0; j < LAT; j++) {
            float acc = 0.0f;
            for (int i = 0; i < LAT; i++) acc = __fmaf_rn(l[i], W0[i*LAT+j], acc);
            acc = __fadd_rn(acc, b0[j]);
            h[j] = sinf(30.0f * acc);
        }
        const float* Ws[3] = {W1, W2, W3};
        const float* bs[3] = {b1, b2, b3};
        for (int L = 0; L < 3; L++) {
            for (int j = 0; j < LAT; j++) {
                float acc = 0.0f;
                for (int i = 0; i < LAT; i++) acc = __fmaf_rn(h[i], Ws[L][i*LAT+j], acc);
                acc = __fadd_rn(acc, bs[L][j]);
                tv[j] = sinf(acc);
            }
            for (int j = 0; j < LAT; j++) h[j] = __fadd_rn(h[j], tv[j]);
        }
        for (int j = 0; j < LAT; j++) g_h[b*LAT+j] = h[j];
    }
}

// ---------------- zero image -------------------------------------------------
__global__ void zero_kernel()
{
    int i = blockIdx.x * blockDim.x + threadIdx.x;
    if (i < IMG_ELEMS) g_img[i] = 0.0f;
}

// ---------------- scatter: rotate, project, delta, atomic add ---------------
// Rotation dot mirrors cuBLAS SGEMM (ascending-k FMA chain from a 0 acc);
// the +shift+half adds mirror XLA's left-associated fp32 adds.
__global__ void scatter_kernel(const float* __restrict__ coords,
                               const float* __restrict__ values,
                               const float* __restrict__ Wd,
                               const float* __restrict__ bd)
{
    __shared__ float sR[Bb*6], sSh[Bb*2], sH[Bb*LAT];
    int t = threadIdx.x;
    if (t < Bb*6)   sR[t]  = g_R[t];
    if (t < Bb*2)   sSh[t] = g_sh[t];
    if (t < Bb*LAT) sH[t]  = g_h[t];
    __syncthreads();

    int n = blockIdx.x * blockDim.x + t;
    if (n >= NPTS) return;

    float c0 = coords[3*n+0];
    float c1 = coords[3*n+1];
    float c2 = coords[3*n+2];
    float val = values[n];
    float bdn = bd[n];

    float wd[LAT];
#pragma unroll
    for (int l = 0; l < LAT; l++) wd[l] = Wd[l*NPTS + n];

#pragma unroll
    for (int b = 0; b < Bb; b++) {
        float x = __fmul_rn(sR[b*6+0], c0);
        x = __fmaf_rn(sR[b*6+1], c1, x);
        x = __fmaf_rn(sR[b*6+2], c2, x);
        float y = __fmul_rn(sR[b*6+3], c0);
        y = __fmaf_rn(sR[b*6+4], c1, y);
        y = __fmaf_rn(sR[b*6+5], c2, y);
        x = __fadd_rn(__fadd_rn(x, sSh[b*2+0]), 128.0f);
        y = __fadd_rn(__fadd_rn(y, sSh[b*2+1]), 128.0f);
        float pxf = fminf(fmaxf(rintf(x), 0.0f), 255.0f);
        float pyf = fminf(fmaxf(rintf(y), 0.0f), 255.0f);
        int px = (int)pxf;
        int py = (int)pyf;

        float d = 0.0f;
#pragma unroll
        for (int l = 0; l < LAT; l++) d = __fmaf_rn(sH[b*LAT+l], wd[l], d);
        // reference: vals = values + (h@Wd + bd)
        float contrib = __fadd_rn(val, __fadd_rn(d, bdn));

        int idx = (b << 16) | (py << 8) | px;
        atomicAdd(&g_img[idx], contrib);
    }
}

// ---------------- separable gaussian blur (zero-padded SAME) ----------------
#define GW0 0.39905027f
#define GW1 0.24203622f
#define GW2 0.05400558f
#define GW3 0.00443305f

__global__ void blur_y_kernel()
{
    int i = blockIdx.x * blockDim.x + threadIdx.x;
    if (i >= IMG_ELEMS) return;
    int x = i & 255, y = (i >> 8) & 255, b = i >> 16;
    const float w[7] = {GW3, GW2, GW1, GW0, GW1, GW2, GW3};
    float acc = 0.0f;
#pragma unroll
    for (int d = -3; d <= 3; d++) {
        int yy = y + d;
        if (yy >= 0 && yy < XS)
            acc += w[d+3] * g_img[(b << 16) | (yy << 8) | x];
    }
    g_tmp[i] = acc;
}

__global__ void blur_x_kernel()
{
    int i = blockIdx.x * blockDim.x + threadIdx.x;
    if (i >= IMG_ELEMS) return;
    int x = i & 255, y = (i >> 8) & 255, b = i >> 16;
    const float w[7] = {GW3, GW2, GW1, GW0, GW1, GW2, GW3};
    float acc = 0.0f;
#pragma unroll
    for (int d = -3; d <= 3; d++) {
        int xx = x + d;
        if (xx >= 0 && xx < XS)
            acc += w[d+3] * g_tmp[(b << 16) | (y << 8) | xx];
    }
    g_img[i] = acc;
}

// ---------------- 256-pt radix-2 DIT FFT (bit-reversed input in smem) -------
__device__ __forceinline__ void fft256(float2* s, const float2* tw, int tid, bool inv)
{
#pragma unroll
    for (int len = 2; len <= 256; len <<= 1) {
        __syncthreads();
        int half = len >> 1;
        int k    = tid & (half - 1);
        int base = (tid & ~(half - 1)) << 1;
        float2 w = tw[k * (256 / len)];
        float wy = inv ? -w.y : w.y;
        float2 u = s[base + k];
        float2 v = s[base + k + half];
        float2 vw = make_float2(v.x*w.x - v.y*wy, v.x*wy + v.y*w.x);
        s[base + k]        = make_float2(u.x + vw.x, u.y + vw.y);
        s[base + k + half] = make_float2(u.x - vw.x, u.y - vw.y);
    }
    __syncthreads();
}

// forward FFT along rows (x axis); real input -> full complex
__global__ void fft_rows_fwd()
{
    __shared__ float2 s[256];
    __shared__ float2 stw[128];
    int tid = threadIdx.x;                 // 0..127
    int off = blockIdx.x << 8;             // (b*256+y)*256
    stw[tid] = g_tw[tid];
    int r0 = __brev(tid) >> 24;
    int r1 = __brev(tid + 128) >> 24;
    s[tid]       = make_float2(g_img[off + r0], 0.0f);
    s[tid + 128] = make_float2(g_img[off + r1], 0.0f);
    fft256(s, stw, tid, false);
    g_F[off + tid]       = s[tid];
    g_F[off + tid + 128] = s[tid + 128];
}

// fused: column fwd FFT  ->  * ctf (Hermitian-extended)  ->  column inv FFT
__global__ void fft_cols_ctf(const float* __restrict__ ctf)
{
    __shared__ float2 s[256];
    __shared__ float2 s2[256];
    __shared__ float2 stw[128];
    int tid = threadIdx.x;
    int bid = blockIdx.x;
    int b = bid >> 8, x = bid & 255;
    int base = (b << 16) + x;
    stw[tid] = g_tw[tid];

    int r0 = __brev(tid) >> 24;
    int r1 = __brev(tid + 128) >> 24;
    s[tid]       = g_F[base + (r0 << 8)];
    s[tid + 128] = g_F[base + (r1 << 8)];
    fft256(s, stw, tid, false);

    // multiply by Hermitian-extended ctf, storing bit-reversed into s2
#pragma unroll
    for (int p = 0; p < 2; p++) {
        int j = tid + p * 128;
        int y = __brev(j) >> 24;
        float c;
        if (x <= 128) {
            c = ctf[(b * 256 + y) * 129 + x];
        } else {
            int yy = (256 - y) & 255;
            c = ctf[(b * 256 + yy) * 129 + (256 - x)];
        }
        float2 v = s[y];
        s2[j] = make_float2(v.x * c, v.y * c);
    }
    fft256(s2, stw, tid, true);   // starts with __syncthreads -> s2 visible

    g_F[base + (tid << 8)]         = s2[tid];
    g_F[base + ((tid + 128) << 8)] = s2[tid + 128];
}

// inverse FFT along rows, take real part, scale by 1/(256*256)
__global__ void fft_rows_inv(float* __restrict__ out)
{
    __shared__ float2 s[256];
    __shared__ float2 stw[128];
    int tid = threadIdx.x;
    int off = blockIdx.x << 8;
    stw[tid] = g_tw[tid];
    int r0 = __brev(tid) >> 24;
    int r1 = __brev(tid + 128) >> 24;
    s[tid]       = g_F[off + r0];
    s[tid + 128] = g_F[off + r1];
    fft256(s, stw, tid, true);
    const float norm = 1.0f / 65536.0f;
    out[off + tid]       = s[tid].x * norm;
    out[off + tid + 128] = s[tid + 128].x * norm;
}

// ---------------- launch -----------------------------------------------------
extern "C" void kernel_launch(void* const* d_in, const int* in_sizes, int n_in,
                              void* d_out, int out_size)
{
    const float* rows   = (const float*)d_in[0];
    const float* shifts = (const float*)d_in[1];
    const float* latent = (const float*)d_in[2];
    const float* coords = (const float*)d_in[3];
    const float* values = (const float*)d_in[4];
    const float* W0     = (const float*)d_in[5];
    const float* b0     = (const float*)d_in[6];
    const float* W1     = (const float*)d_in[7];
    const float* b1     = (const float*)d_in[8];
    const float* W2     = (const float*)d_in[9];
    const float* b2     = (const float*)d_in[10];
    const float* W3     = (const float*)d_in[11];
    const float* b3     = (const float*)d_in[12];
    const float* Wd     = (const float*)d_in[13];
    const float* bd     = (const float*)d_in[14];
    const float* ctf    = (const float*)d_in[15];
    float* out = (float*)d_out;

    prep_kernel<<<1, 128>>>(rows, shifts, latent, W0, b0, W1, b1, W2, b2, W3, b3);
    zero_kernel<<<IMG_ELEMS / 256, 256>>>();
    scatter_kernel<<<(NPTS + 255) / 256, 256>>>(coords, values, Wd, bd);
    blur_y_kernel<<<IMG_ELEMS / 256, 256>>>();
    blur_x_kernel<<<IMG_ELEMS / 256, 256>>>();
    fft_rows_fwd<<<Bb * XS, 128>>>();
    fft_cols_ctf<<<Bb * XS, 128>>>(ctf);
    fft_rows_inv<<<Bb * XS, 128>>>(out);
}